// round 5
// baseline (speedup 1.0000x reference)
#include <cuda_runtime.h>
#include <cuda_fp16.h>
#include <cuda_bf16.h>

// Problem constants
#define N_NODES   100000
#define N_EDGES   1600000
#define DIM       128
#define N_GRAPHS  1024
#define SCAN_BLOCKS 98          // ceil(100000/1024)

// ---------------- scratch (__device__ globals: allocation-free) ----------------
__device__ __half g_h16a[(size_t)N_NODES * DIM];  // 25.6 MB: x (fp16), later h1 (fp16)
__device__ __half g_agg16[(size_t)N_NODES * DIM]; // 25.6 MB: agg1 output (fp16)
__device__ float  g_bufA[(size_t)N_NODES * DIM];  // 51.2 MB: agg2 output (fp32)
__device__ int    g_cnt[N_NODES];
__device__ float  g_dinv[N_NODES];
__device__ int    g_rowptr[N_NODES + 1];
__device__ int    g_cursor[N_NODES];
__device__ int    g_srcsorted[N_EDGES];
__device__ int    g_blocksums[SCAN_BLOCKS];
__device__ int    g_blockoff[SCAN_BLOCKS];

// ---------------- zero in-degree ----------------
__global__ void zero_kernel() {
    int i = blockIdx.x * blockDim.x + threadIdx.x;
    if (i < N_NODES) g_cnt[i] = 0;
}

// ---------------- fp32 -> fp16 convert (x) ----------------
__global__ void tohalf_kernel(const float* __restrict__ x, __half* __restrict__ o) {
    int i = blockIdx.x * blockDim.x + threadIdx.x;           // float4 index
    const int total = N_NODES * DIM / 4;
    int stride = gridDim.x * blockDim.x;
    for (int j = i; j < total; j += stride) {
        float4 v = reinterpret_cast<const float4*>(x)[j];
        __half2 h0 = __floats2half2_rn(v.x, v.y);
        __half2 h1 = __floats2half2_rn(v.z, v.w);
        uint2 st;
        st.x = *reinterpret_cast<unsigned*>(&h0);
        st.y = *reinterpret_cast<unsigned*>(&h1);
        reinterpret_cast<uint2*>(o)[j] = st;
    }
}

// ---------------- degree histogram over dst ----------------
__global__ void hist_kernel(const int* __restrict__ dst) {
    int i = blockIdx.x * blockDim.x + threadIdx.x;
    int stride = gridDim.x * blockDim.x;
    for (int e = i; e < N_EDGES; e += stride)
        atomicAdd(&g_cnt[dst[e]], 1);
}

// ---------------- scan phase A: per-block exclusive scan + dinv ----------------
__global__ void scanA_kernel() {
    __shared__ int warp_sums[32];
    int tid = threadIdx.x, lane = tid & 31, wid = tid >> 5;
    int i = blockIdx.x * 1024 + tid;
    int v = (i < N_NODES) ? g_cnt[i] : 0;
    if (i < N_NODES) g_dinv[i] = rsqrtf((float)(v + 1));

    int x = v;
    #pragma unroll
    for (int o = 1; o < 32; o <<= 1) {
        int t = __shfl_up_sync(0xffffffffu, x, o);
        if (lane >= o) x += t;
    }
    if (lane == 31) warp_sums[wid] = x;
    __syncthreads();
    if (wid == 0) {
        int s = warp_sums[lane];
        #pragma unroll
        for (int o = 1; o < 32; o <<= 1) {
            int t = __shfl_up_sync(0xffffffffu, s, o);
            if (lane >= o) s += t;
        }
        warp_sums[lane] = s;
    }
    __syncthreads();
    int excl = (wid > 0 ? warp_sums[wid - 1] : 0) + x - v;
    if (i < N_NODES) g_rowptr[i] = excl;
    if (tid == 0) g_blocksums[blockIdx.x] = warp_sums[31];
}

// ---------------- scan phase B ----------------
__global__ void scanB_kernel() {
    __shared__ int s[128];
    int tid = threadIdx.x;
    s[tid] = (tid < SCAN_BLOCKS) ? g_blocksums[tid] : 0;
    __syncthreads();
    #pragma unroll
    for (int o = 1; o < 128; o <<= 1) {
        int t = (tid >= o) ? s[tid - o] : 0;
        __syncthreads();
        s[tid] += t;
        __syncthreads();
    }
    if (tid < SCAN_BLOCKS)
        g_blockoff[tid] = (tid > 0) ? s[tid - 1] : 0;
}

// ---------------- scan phase C ----------------
__global__ void scanC_kernel() {
    int i = blockIdx.x * 1024 + threadIdx.x;
    if (i < N_NODES) {
        int r = g_rowptr[i] + g_blockoff[blockIdx.x];
        g_rowptr[i] = r;
        g_cursor[i] = r;
    }
    if (i == 0) g_rowptr[N_NODES] = N_EDGES;
}

// ---------------- counting-sort fill ----------------
__global__ void fill_kernel(const int* __restrict__ src, const int* __restrict__ dst) {
    int i = blockIdx.x * blockDim.x + threadIdx.x;
    int stride = gridDim.x * blockDim.x;
    for (int e = i; e < N_EDGES; e += stride) {
        int d = dst[e];
        int pos = atomicAdd(&g_cursor[d], 1);
        g_srcsorted[pos] = src[e];
    }
}

// ---------------- aggregation (fp16 gather, fp32 accumulate) ----------------
// one warp per node; each lane owns 4 features (8 bytes/row as uint2)
// OUT_HALF=1: write __half, OUT_HALF=0: write float (float4)
template <int OUT_HALF>
__global__ void agg_kernel_h(const __half* __restrict__ feat, void* __restrict__ out) {
    int gtid = blockIdx.x * blockDim.x + threadIdx.x;
    int node = gtid >> 5;
    int lane = gtid & 31;
    if (node >= N_NODES) return;

    float di = g_dinv[node];
    const uint2* self_row = reinterpret_cast<const uint2*>(feat + (size_t)node * DIM);
    uint2 sv = self_row[lane];
    __half2 sh0 = *reinterpret_cast<__half2*>(&sv.x);
    __half2 sh1 = *reinterpret_cast<__half2*>(&sv.y);
    float2 sf0 = __half22float2(sh0);
    float2 sf1 = __half22float2(sh1);
    float wsl = di * di;
    float4 acc = make_float4(wsl * sf0.x, wsl * sf0.y, wsl * sf1.x, wsl * sf1.y);

    int e0 = g_rowptr[node];
    int e1 = g_rowptr[node + 1];
    for (int eb = e0; eb < e1; eb += 32) {
        int nb = min(32, e1 - eb);
        int s = 0; float w = 0.0f;
        if (lane < nb) {
            s = g_srcsorted[eb + lane];
            w = di * g_dinv[s];
        }
        for (int j = 0; j < nb; ++j) {
            int sj  = __shfl_sync(0xffffffffu, s, j);
            float wj = __shfl_sync(0xffffffffu, w, j);
            uint2 d = reinterpret_cast<const uint2*>(feat + (size_t)sj * DIM)[lane];
            __half2 h0 = *reinterpret_cast<__half2*>(&d.x);
            __half2 h1 = *reinterpret_cast<__half2*>(&d.y);
            float2 f0 = __half22float2(h0);
            float2 f1 = __half22float2(h1);
            acc.x += wj * f0.x; acc.y += wj * f0.y;
            acc.z += wj * f1.x; acc.w += wj * f1.y;
        }
    }
    if (OUT_HALF) {
        __half2 o0 = __floats2half2_rn(acc.x, acc.y);
        __half2 o1 = __floats2half2_rn(acc.z, acc.w);
        uint2 st;
        st.x = *reinterpret_cast<unsigned*>(&o0);
        st.y = *reinterpret_cast<unsigned*>(&o1);
        reinterpret_cast<uint2*>((__half*)out + (size_t)node * DIM)[lane] = st;
    } else {
        reinterpret_cast<float4*>((float*)out + (size_t)node * DIM)[lane] = acc;
    }
}

// ---------------- GEMM: C = relu(A @ W + b), A fp16, W/b fp32, C fp16 --------
#define BM 64
#define BK 32
__global__ void gemm_bias_relu_h(const __half* __restrict__ A, const float* __restrict__ W,
                                 const float* __restrict__ bias, __half* __restrict__ C,
                                 int M) {
    __shared__ float As[BK][BM];    // transposed A tile
    __shared__ float Ws[BK][DIM];
    int tid = threadIdx.x;          // 256
    int tx = tid & 31;              // 4 output cols
    int ty = tid >> 5;              // 8 output rows
    int row0 = blockIdx.x * BM;

    float acc[8][4];
    #pragma unroll
    for (int i = 0; i < 8; ++i)
        #pragma unroll
        for (int j = 0; j < 4; ++j) acc[i][j] = 0.0f;

    for (int k0 = 0; k0 < DIM; k0 += BK) {
        // A tile: 64 rows x 32 halves. 256 thr: r = tid>>2, 8 halves per thread
        {
            int r = tid >> 2;
            int c0 = (tid & 3) * 8;
            int grow = min(row0 + r, M - 1);
            uint4 d = *reinterpret_cast<const uint4*>(A + (size_t)grow * DIM + k0 + c0);
            __half2 h0 = *reinterpret_cast<__half2*>(&d.x);
            __half2 h1 = *reinterpret_cast<__half2*>(&d.y);
            __half2 h2 = *reinterpret_cast<__half2*>(&d.z);
            __half2 h3 = *reinterpret_cast<__half2*>(&d.w);
            float2 f0 = __half22float2(h0), f1 = __half22float2(h1);
            float2 f2 = __half22float2(h2), f3 = __half22float2(h3);
            As[c0 + 0][r] = f0.x; As[c0 + 1][r] = f0.y;
            As[c0 + 2][r] = f1.x; As[c0 + 3][r] = f1.y;
            As[c0 + 4][r] = f2.x; As[c0 + 5][r] = f2.y;
            As[c0 + 6][r] = f3.x; As[c0 + 7][r] = f3.y;
        }
        // W tile (32 x 128), contiguous fp32
        const float4* Wg = reinterpret_cast<const float4*>(W + (size_t)k0 * DIM);
        float4* Wsv = reinterpret_cast<float4*>(&Ws[0][0]);
        #pragma unroll
        for (int i = 0; i < 4; ++i) {
            int f4 = i * 256 + tid;
            Wsv[f4] = Wg[f4];
        }
        __syncthreads();

        #pragma unroll
        for (int k = 0; k < BK; ++k) {
            float4 w  = *reinterpret_cast<const float4*>(&Ws[k][tx * 4]);
            float4 a0 = *reinterpret_cast<const float4*>(&As[k][ty * 8]);
            float4 a1 = *reinterpret_cast<const float4*>(&As[k][ty * 8 + 4]);
            float ar[8] = {a0.x, a0.y, a0.z, a0.w, a1.x, a1.y, a1.z, a1.w};
            #pragma unroll
            for (int i = 0; i < 8; ++i) {
                acc[i][0] += ar[i] * w.x;
                acc[i][1] += ar[i] * w.y;
                acc[i][2] += ar[i] * w.z;
                acc[i][3] += ar[i] * w.w;
            }
        }
        __syncthreads();
    }

    float4 b = *reinterpret_cast<const float4*>(&bias[tx * 4]);
    #pragma unroll
    for (int i = 0; i < 8; ++i) {
        int row = row0 + ty * 8 + i;
        if (row < M) {
            float ox = fmaxf(acc[i][0] + b.x, 0.0f);
            float oy = fmaxf(acc[i][1] + b.y, 0.0f);
            float oz = fmaxf(acc[i][2] + b.z, 0.0f);
            float ow = fmaxf(acc[i][3] + b.w, 0.0f);
            __half2 h0 = __floats2half2_rn(ox, oy);
            __half2 h1 = __floats2half2_rn(oz, ow);
            uint2 st;
            st.x = *reinterpret_cast<unsigned*>(&h0);
            st.y = *reinterpret_cast<unsigned*>(&h1);
            *reinterpret_cast<uint2*>(C + (size_t)row * DIM + tx * 4) = st;
        }
    }
}

// ---------------- fused mean-pool (sorted batch) + W2 GEMM + b2 --------------
__global__ void pool_gemm_kernel(const float* __restrict__ feat,
                                 const int* __restrict__ batch,
                                 const float* __restrict__ W2,
                                 const float* __restrict__ b2,
                                 float* __restrict__ out) {
    __shared__ float p[DIM];
    int g = blockIdx.x;
    int j = threadIdx.x;   // 128

    int lo = 0, hi = N_NODES;
    while (lo < hi) { int m = (lo + hi) >> 1; if (batch[m] < g) lo = m + 1; else hi = m; }
    int start = lo;
    hi = N_NODES;
    while (lo < hi) { int m = (lo + hi) >> 1; if (batch[m] < g + 1) lo = m + 1; else hi = m; }
    int end = lo;

    float acc = 0.0f;
    for (int n = start; n < end; ++n)
        acc += feat[(size_t)n * DIM + j];
    float cnt = fmaxf((float)(end - start), 1.0f);
    p[j] = acc / cnt;
    __syncthreads();

    float o = b2[j];
    #pragma unroll 8
    for (int k = 0; k < DIM; ++k)
        o += p[k] * W2[k * DIM + j];
    out[g * DIM + j] = o;
}

// ---------------- launch ----------------
extern "C" void kernel_launch(void* const* d_in, const int* in_sizes, int n_in,
                              void* d_out, int out_size) {
    const float* x     = (const float*)d_in[0];
    const int*   ei    = (const int*)d_in[1];
    const int*   batch = (const int*)d_in[2];
    const float* W1    = (const float*)d_in[3];
    const float* b1    = (const float*)d_in[4];
    const float* W2    = (const float*)d_in[5];
    const float* b2    = (const float*)d_in[6];
    float* out = (float*)d_out;

    const int* src = ei;            // edge_index[0]
    const int* dst = ei + N_EDGES;  // edge_index[1]

    __half* h16a;  cudaGetSymbolAddress((void**)&h16a,  g_h16a);
    __half* agg16; cudaGetSymbolAddress((void**)&agg16, g_agg16);
    float*  bufA;  cudaGetSymbolAddress((void**)&bufA,  g_bufA);

    zero_kernel<<<(N_NODES + 1023) / 1024, 1024>>>();
    tohalf_kernel<<<1024, 256>>>(x, h16a);
    hist_kernel<<<2048, 256>>>(dst);
    scanA_kernel<<<SCAN_BLOCKS, 1024>>>();
    scanB_kernel<<<1, 128>>>();
    scanC_kernel<<<SCAN_BLOCKS, 1024>>>();
    fill_kernel<<<2048, 256>>>(src, dst);

    int agg_blocks = (N_NODES * 32 + 255) / 256;
    // layer 1: agg(x16) -> agg16 (fp16); h1 = relu(agg16 @ W1 + b1) -> h16a (fp16)
    agg_kernel_h<1><<<agg_blocks, 256>>>(h16a, agg16);
    gemm_bias_relu_h<<<(N_NODES + BM - 1) / BM, 256>>>(agg16, W1, b1, h16a, N_NODES);

    // layer 2: agg(h1) -> bufA (fp32); W2 deferred past pooling
    agg_kernel_h<0><<<agg_blocks, 256>>>(h16a, bufA);

    // fused mean-pool + W2 GEMM + b2
    pool_gemm_kernel<<<N_GRAPHS, DIM>>>(bufA, batch, W2, b2, out);
}

// round 6
// speedup vs baseline: 1.4324x; 1.4324x over previous
#include <cuda_runtime.h>
#include <cuda_fp16.h>
#include <cuda_bf16.h>

// Problem constants
#define N_NODES   100000
#define N_EDGES   1600000
#define DIM       128
#define N_GRAPHS  1024
#define SCAN_BLOCKS 98          // ceil(100000/1024)

// ---------------- scratch (__device__ globals: allocation-free) ----------------
__device__ unsigned g_bfA[(size_t)N_NODES * DIM / 2]; // 25.6 MB bf16x2: x16, later h1
__device__ unsigned g_bfB[(size_t)N_NODES * DIM / 2]; // 25.6 MB bf16x2: agg1 out
__device__ float    g_bufF[(size_t)N_NODES * DIM];    // 51.2 MB fp32: agg2 out
__device__ int2     g_edge[N_EDGES];                  // 12.8 MB: (src, dinv[src] bits)
__device__ int      g_cnt[N_NODES];
__device__ float    g_dinv[N_NODES];
__device__ int      g_rowptr[N_NODES + 1];
__device__ int      g_cursor[N_NODES];
__device__ int      g_blocksums[SCAN_BLOCKS];
__device__ int      g_blockoff[SCAN_BLOCKS];

// bf16x2 (packed in u32) -> two fp32, pure ALU (SHF/LOP3), no F2F
__device__ __forceinline__ float2 bf2f(unsigned u) {
    float2 r;
    r.x = __uint_as_float(u << 16);
    r.y = __uint_as_float(u & 0xFFFF0000u);
    return r;
}
// two fp32 -> bf16x2 packed u32 (F2FP: fixed-lat pipe, cheap)
__device__ __forceinline__ unsigned f2bf(float a, float b) {
    __nv_bfloat162 h = __floats2bfloat162_rn(a, b);
    return *reinterpret_cast<unsigned*>(&h);
}

// ---------------- zero in-degree ----------------
__global__ void zero_kernel() {
    int i = blockIdx.x * blockDim.x + threadIdx.x;
    if (i < N_NODES) g_cnt[i] = 0;
}

// ---------------- fp32 -> bf16 convert (x) ----------------
__global__ void tobf16_kernel(const float* __restrict__ x, unsigned* __restrict__ o) {
    int i = blockIdx.x * blockDim.x + threadIdx.x;
    const int total = N_NODES * DIM / 4;         // float4 / uint2 count
    int stride = gridDim.x * blockDim.x;
    for (int j = i; j < total; j += stride) {
        float4 v = reinterpret_cast<const float4*>(x)[j];
        uint2 st;
        st.x = f2bf(v.x, v.y);
        st.y = f2bf(v.z, v.w);
        reinterpret_cast<uint2*>(o)[j] = st;
    }
}

// ---------------- degree histogram over dst ----------------
__global__ void hist_kernel(const int* __restrict__ dst) {
    int i = blockIdx.x * blockDim.x + threadIdx.x;
    int stride = gridDim.x * blockDim.x;
    for (int e = i; e < N_EDGES; e += stride)
        atomicAdd(&g_cnt[dst[e]], 1);
}

// ---------------- scan phase A: per-block exclusive scan + dinv ----------------
__global__ void scanA_kernel() {
    __shared__ int warp_sums[32];
    int tid = threadIdx.x, lane = tid & 31, wid = tid >> 5;
    int i = blockIdx.x * 1024 + tid;
    int v = (i < N_NODES) ? g_cnt[i] : 0;
    if (i < N_NODES) g_dinv[i] = rsqrtf((float)(v + 1));

    int x = v;
    #pragma unroll
    for (int o = 1; o < 32; o <<= 1) {
        int t = __shfl_up_sync(0xffffffffu, x, o);
        if (lane >= o) x += t;
    }
    if (lane == 31) warp_sums[wid] = x;
    __syncthreads();
    if (wid == 0) {
        int s = warp_sums[lane];
        #pragma unroll
        for (int o = 1; o < 32; o <<= 1) {
            int t = __shfl_up_sync(0xffffffffu, s, o);
            if (lane >= o) s += t;
        }
        warp_sums[lane] = s;
    }
    __syncthreads();
    int excl = (wid > 0 ? warp_sums[wid - 1] : 0) + x - v;
    if (i < N_NODES) g_rowptr[i] = excl;
    if (tid == 0) g_blocksums[blockIdx.x] = warp_sums[31];
}

// ---------------- scan phase B ----------------
__global__ void scanB_kernel() {
    __shared__ int s[128];
    int tid = threadIdx.x;
    s[tid] = (tid < SCAN_BLOCKS) ? g_blocksums[tid] : 0;
    __syncthreads();
    #pragma unroll
    for (int o = 1; o < 128; o <<= 1) {
        int t = (tid >= o) ? s[tid - o] : 0;
        __syncthreads();
        s[tid] += t;
        __syncthreads();
    }
    if (tid < SCAN_BLOCKS)
        g_blockoff[tid] = (tid > 0) ? s[tid - 1] : 0;
}

// ---------------- scan phase C ----------------
__global__ void scanC_kernel() {
    int i = blockIdx.x * 1024 + threadIdx.x;
    if (i < N_NODES) {
        int r = g_rowptr[i] + g_blockoff[blockIdx.x];
        g_rowptr[i] = r;
        g_cursor[i] = r;
    }
    if (i == 0) g_rowptr[N_NODES] = N_EDGES;
}

// ---------------- counting-sort fill: (src, dinv[src]) records -------------
__global__ void fill_kernel(const int* __restrict__ src, const int* __restrict__ dst) {
    int i = blockIdx.x * blockDim.x + threadIdx.x;
    int stride = gridDim.x * blockDim.x;
    for (int e = i; e < N_EDGES; e += stride) {
        int d = dst[e];
        int s = src[e];
        int pos = atomicAdd(&g_cursor[d], 1);
        g_edge[pos] = make_int2(s, __float_as_int(g_dinv[s]));
    }
}

// ---------------- aggregation (bf16 gather, fp32 accumulate) ----------------
// one warp per node; each lane owns 4 features (one uint2 = 4 bf16 per row)
// OUT_BF16=1: write packed bf16, OUT_BF16=0: write float4
template <int OUT_BF16>
__global__ void agg_kernel_bf(const unsigned* __restrict__ feat, void* __restrict__ out) {
    int gtid = blockIdx.x * blockDim.x + threadIdx.x;
    int node = gtid >> 5;
    int lane = gtid & 31;
    if (node >= N_NODES) return;

    float di = g_dinv[node];
    const uint2* row = reinterpret_cast<const uint2*>(feat + (size_t)node * (DIM / 2));
    uint2 sv = row[lane];
    float2 s0 = bf2f(sv.x), s1 = bf2f(sv.y);
    float wsl = di * di;
    float4 acc = make_float4(wsl * s0.x, wsl * s0.y, wsl * s1.x, wsl * s1.y);

    int e0 = g_rowptr[node];
    int e1 = g_rowptr[node + 1];
    for (int eb = e0; eb < e1; eb += 32) {
        int nb = min(32, e1 - eb);
        int2 ew = make_int2(0, 0);
        float wown = 0.0f;
        if (lane < nb) {
            ew = g_edge[eb + lane];
            wown = di * __int_as_float(ew.y);
        }
        for (int j = 0; j < nb; ++j) {
            int sj   = __shfl_sync(0xffffffffu, ew.x, j);
            float wj = __shfl_sync(0xffffffffu, wown, j);
            uint2 d = reinterpret_cast<const uint2*>(feat + (size_t)sj * (DIM / 2))[lane];
            float2 f0 = bf2f(d.x), f1 = bf2f(d.y);
            acc.x += wj * f0.x; acc.y += wj * f0.y;
            acc.z += wj * f1.x; acc.w += wj * f1.y;
        }
    }
    if (OUT_BF16) {
        uint2 st;
        st.x = f2bf(acc.x, acc.y);
        st.y = f2bf(acc.z, acc.w);
        reinterpret_cast<uint2*>((unsigned*)out + (size_t)node * (DIM / 2))[lane] = st;
    } else {
        reinterpret_cast<float4*>((float*)out + (size_t)node * DIM)[lane] = acc;
    }
}

// ---------------- GEMM: C = relu(A @ W + b), A bf16, W/b fp32, C bf16 --------
#define BM 64
#define BK 32
__global__ void gemm_bias_relu_bf(const unsigned* __restrict__ A, const float* __restrict__ W,
                                  const float* __restrict__ bias, unsigned* __restrict__ C,
                                  int M) {
    __shared__ float As[BK][BM];    // transposed A tile
    __shared__ float Ws[BK][DIM];
    int tid = threadIdx.x;          // 256
    int tx = tid & 31;              // 4 output cols
    int ty = tid >> 5;              // 8 output rows
    int row0 = blockIdx.x * BM;

    float acc[8][4];
    #pragma unroll
    for (int i = 0; i < 8; ++i)
        #pragma unroll
        for (int j = 0; j < 4; ++j) acc[i][j] = 0.0f;

    for (int k0 = 0; k0 < DIM; k0 += BK) {
        // A tile: 64 rows x 32 bf16. 4 threads/row, each loads uint4 = 8 bf16
        {
            int r  = tid >> 2;
            int c0 = (tid & 3) * 8;
            int grow = min(row0 + r, M - 1);
            uint4 d = *reinterpret_cast<const uint4*>(
                A + (size_t)grow * (DIM / 2) + (k0 + c0) / 2);
            float2 f0 = bf2f(d.x), f1 = bf2f(d.y), f2 = bf2f(d.z), f3 = bf2f(d.w);
            As[c0 + 0][r] = f0.x; As[c0 + 1][r] = f0.y;
            As[c0 + 2][r] = f1.x; As[c0 + 3][r] = f1.y;
            As[c0 + 4][r] = f2.x; As[c0 + 5][r] = f2.y;
            As[c0 + 6][r] = f3.x; As[c0 + 7][r] = f3.y;
        }
        // W tile (32 x 128), contiguous fp32
        const float4* Wg = reinterpret_cast<const float4*>(W + (size_t)k0 * DIM);
        float4* Wsv = reinterpret_cast<float4*>(&Ws[0][0]);
        #pragma unroll
        for (int i = 0; i < 4; ++i) {
            int f4 = i * 256 + tid;
            Wsv[f4] = Wg[f4];
        }
        __syncthreads();

        #pragma unroll
        for (int k = 0; k < BK; ++k) {
            float4 w  = *reinterpret_cast<const float4*>(&Ws[k][tx * 4]);
            float4 a0 = *reinterpret_cast<const float4*>(&As[k][ty * 8]);
            float4 a1 = *reinterpret_cast<const float4*>(&As[k][ty * 8 + 4]);
            float ar[8] = {a0.x, a0.y, a0.z, a0.w, a1.x, a1.y, a1.z, a1.w};
            #pragma unroll
            for (int i = 0; i < 8; ++i) {
                acc[i][0] += ar[i] * w.x;
                acc[i][1] += ar[i] * w.y;
                acc[i][2] += ar[i] * w.z;
                acc[i][3] += ar[i] * w.w;
            }
        }
        __syncthreads();
    }

    float4 b = *reinterpret_cast<const float4*>(&bias[tx * 4]);
    #pragma unroll
    for (int i = 0; i < 8; ++i) {
        int row = row0 + ty * 8 + i;
        if (row < M) {
            float ox = fmaxf(acc[i][0] + b.x, 0.0f);
            float oy = fmaxf(acc[i][1] + b.y, 0.0f);
            float oz = fmaxf(acc[i][2] + b.z, 0.0f);
            float ow = fmaxf(acc[i][3] + b.w, 0.0f);
            uint2 st;
            st.x = f2bf(ox, oy);
            st.y = f2bf(oz, ow);
            *reinterpret_cast<uint2*>(C + (size_t)row * (DIM / 2) + tx * 2) = st;
        }
    }
}

// ---------------- fused mean-pool (sorted batch) + W2 GEMM + b2 --------------
__global__ void pool_gemm_kernel(const float* __restrict__ feat,
                                 const int* __restrict__ batch,
                                 const float* __restrict__ W2,
                                 const float* __restrict__ b2,
                                 float* __restrict__ out) {
    __shared__ float p[DIM];
    int g = blockIdx.x;
    int j = threadIdx.x;   // 128

    int lo = 0, hi = N_NODES;
    while (lo < hi) { int m = (lo + hi) >> 1; if (batch[m] < g) lo = m + 1; else hi = m; }
    int start = lo;
    hi = N_NODES;
    while (lo < hi) { int m = (lo + hi) >> 1; if (batch[m] < g + 1) lo = m + 1; else hi = m; }
    int end = lo;

    float acc = 0.0f;
    for (int n = start; n < end; ++n)
        acc += feat[(size_t)n * DIM + j];
    float cnt = fmaxf((float)(end - start), 1.0f);
    p[j] = acc / cnt;
    __syncthreads();

    float o = b2[j];
    #pragma unroll 8
    for (int k = 0; k < DIM; ++k)
        o += p[k] * W2[k * DIM + j];
    out[g * DIM + j] = o;
}

// ---------------- launch ----------------
extern "C" void kernel_launch(void* const* d_in, const int* in_sizes, int n_in,
                              void* d_out, int out_size) {
    const float* x     = (const float*)d_in[0];
    const int*   ei    = (const int*)d_in[1];
    const int*   batch = (const int*)d_in[2];
    const float* W1    = (const float*)d_in[3];
    const float* b1    = (const float*)d_in[4];
    const float* W2    = (const float*)d_in[5];
    const float* b2    = (const float*)d_in[6];
    float* out = (float*)d_out;

    const int* src = ei;            // edge_index[0]
    const int* dst = ei + N_EDGES;  // edge_index[1]

    unsigned* bfA; cudaGetSymbolAddress((void**)&bfA, g_bfA);
    unsigned* bfB; cudaGetSymbolAddress((void**)&bfB, g_bfB);
    float*    bufF; cudaGetSymbolAddress((void**)&bufF, g_bufF);

    zero_kernel<<<(N_NODES + 1023) / 1024, 1024>>>();
    tobf16_kernel<<<1024, 256>>>(x, bfA);
    hist_kernel<<<2048, 256>>>(dst);
    scanA_kernel<<<SCAN_BLOCKS, 1024>>>();
    scanB_kernel<<<1, 128>>>();
    scanC_kernel<<<SCAN_BLOCKS, 1024>>>();
    fill_kernel<<<2048, 256>>>(src, dst);

    int agg_blocks = (N_NODES * 32 + 255) / 256;
    // layer 1: agg(x_bf16) -> bfB (bf16); h1 = relu(bfB @ W1 + b1) -> bfA (bf16)
    agg_kernel_bf<1><<<agg_blocks, 256>>>(bfA, bfB);
    gemm_bias_relu_bf<<<(N_NODES + BM - 1) / BM, 256>>>(bfB, W1, b1, bfA, N_NODES);

    // layer 2: agg(h1) -> bufF (fp32); W2 deferred past pooling
    agg_kernel_bf<0><<<agg_blocks, 256>>>(bfA, bufF);

    // fused mean-pool + W2 GEMM + b2
    pool_gemm_kernel<<<N_GRAPHS, DIM>>>(bufF, batch, W2, b2, out);
}

// round 7
// speedup vs baseline: 1.7979x; 1.2552x over previous
#include <cuda_runtime.h>
#include <cuda_fp16.h>
#include <cuda_bf16.h>

// Problem constants
#define N_NODES   100000
#define N_EDGES   1600000
#define DIM       128
#define N_GRAPHS  1024
#define SCAN_BLOCKS 98          // ceil(100000/1024)

// ---------------- scratch (__device__ globals: allocation-free) ----------------
__device__ unsigned g_bfA[(size_t)N_NODES * DIM / 2]; // 25.6 MB bf16x2: x16 / h1
__device__ unsigned g_bfB[(size_t)N_NODES * DIM / 2]; // 25.6 MB bf16x2: agg out
__device__ unsigned g_W1t[DIM * DIM / 2];             // W1^T in bf16: Wt[n][k]
__device__ int2     g_edge[N_EDGES];                  // (src, dinv[src] bits)
__device__ int      g_cnt[N_NODES];
__device__ float    g_dinv[N_NODES];
__device__ int      g_rowptr[N_NODES + 1];
__device__ int      g_cursor[N_NODES];
__device__ int      g_blocksums[SCAN_BLOCKS];
__device__ int      g_blockoff[SCAN_BLOCKS];

// bf16x2 (packed u32) -> two fp32: pure ALU (SHF/LOP3)
__device__ __forceinline__ float2 bf2f(unsigned u) {
    float2 r;
    r.x = __uint_as_float(u << 16);
    r.y = __uint_as_float(u & 0xFFFF0000u);
    return r;
}
// two fp32 -> packed bf16x2 (F2FP, fixed-lat pipe)
__device__ __forceinline__ unsigned f2bf(float a, float b) {
    __nv_bfloat162 h = __floats2bfloat162_rn(a, b);
    return *reinterpret_cast<unsigned*>(&h);
}

// ---------------- zero in-degree ----------------
__global__ void zero_kernel() {
    int i = blockIdx.x * blockDim.x + threadIdx.x;
    if (i < N_NODES) g_cnt[i] = 0;
}

// ---------------- fp32 -> bf16 convert (x) ----------------
__global__ void tobf16_kernel(const float* __restrict__ x, unsigned* __restrict__ o) {
    int i = blockIdx.x * blockDim.x + threadIdx.x;
    const int total = N_NODES * DIM / 4;
    int stride = gridDim.x * blockDim.x;
    for (int j = i; j < total; j += stride) {
        float4 v = reinterpret_cast<const float4*>(x)[j];
        uint2 st;
        st.x = f2bf(v.x, v.y);
        st.y = f2bf(v.z, v.w);
        reinterpret_cast<uint2*>(o)[j] = st;
    }
}

// ---------------- W1 -> bf16 transpose: Wt[n][k] = W1[k][n] ----------------
__global__ void wconv_kernel(const float* __restrict__ W1) {
    int i = blockIdx.x * blockDim.x + threadIdx.x;   // 0..8191 (bf16x2 slots)
    if (i < DIM * DIM / 2) {
        int n = i >> 6;                // 64 u32 per n-row
        int k2 = (i & 63) * 2;         // k pair
        float a = W1[(size_t)k2 * DIM + n];
        float b = W1[(size_t)(k2 + 1) * DIM + n];
        g_W1t[i] = f2bf(a, b);
    }
}

// ---------------- degree histogram over dst ----------------
__global__ void hist_kernel(const int* __restrict__ dst) {
    int i = blockIdx.x * blockDim.x + threadIdx.x;
    int stride = gridDim.x * blockDim.x;
    for (int e = i; e < N_EDGES; e += stride)
        atomicAdd(&g_cnt[dst[e]], 1);
}

// ---------------- scan phase A ----------------
__global__ void scanA_kernel() {
    __shared__ int warp_sums[32];
    int tid = threadIdx.x, lane = tid & 31, wid = tid >> 5;
    int i = blockIdx.x * 1024 + tid;
    int v = (i < N_NODES) ? g_cnt[i] : 0;
    if (i < N_NODES) g_dinv[i] = rsqrtf((float)(v + 1));

    int x = v;
    #pragma unroll
    for (int o = 1; o < 32; o <<= 1) {
        int t = __shfl_up_sync(0xffffffffu, x, o);
        if (lane >= o) x += t;
    }
    if (lane == 31) warp_sums[wid] = x;
    __syncthreads();
    if (wid == 0) {
        int s = warp_sums[lane];
        #pragma unroll
        for (int o = 1; o < 32; o <<= 1) {
            int t = __shfl_up_sync(0xffffffffu, s, o);
            if (lane >= o) s += t;
        }
        warp_sums[lane] = s;
    }
    __syncthreads();
    int excl = (wid > 0 ? warp_sums[wid - 1] : 0) + x - v;
    if (i < N_NODES) g_rowptr[i] = excl;
    if (tid == 0) g_blocksums[blockIdx.x] = warp_sums[31];
}

// ---------------- scan phase B ----------------
__global__ void scanB_kernel() {
    __shared__ int s[128];
    int tid = threadIdx.x;
    s[tid] = (tid < SCAN_BLOCKS) ? g_blocksums[tid] : 0;
    __syncthreads();
    #pragma unroll
    for (int o = 1; o < 128; o <<= 1) {
        int t = (tid >= o) ? s[tid - o] : 0;
        __syncthreads();
        s[tid] += t;
        __syncthreads();
    }
    if (tid < SCAN_BLOCKS)
        g_blockoff[tid] = (tid > 0) ? s[tid - 1] : 0;
}

// ---------------- scan phase C ----------------
__global__ void scanC_kernel() {
    int i = blockIdx.x * 1024 + threadIdx.x;
    if (i < N_NODES) {
        int r = g_rowptr[i] + g_blockoff[blockIdx.x];
        g_rowptr[i] = r;
        g_cursor[i] = r;
    }
    if (i == 0) g_rowptr[N_NODES] = N_EDGES;
}

// ---------------- counting-sort fill: (src, dinv[src]) records -------------
__global__ void fill_kernel(const int* __restrict__ src, const int* __restrict__ dst) {
    int i = blockIdx.x * blockDim.x + threadIdx.x;
    int stride = gridDim.x * blockDim.x;
    for (int e = i; e < N_EDGES; e += stride) {
        int d = dst[e];
        int s = src[e];
        int pos = atomicAdd(&g_cursor[d], 1);
        g_edge[pos] = make_int2(s, __float_as_int(g_dinv[s]));
    }
}

// ---------------- aggregation (bf16 gather, fp32 accumulate, bf16 out) ------
__global__ void agg_kernel_bf(const unsigned* __restrict__ feat, unsigned* __restrict__ out) {
    int gtid = blockIdx.x * blockDim.x + threadIdx.x;
    int node = gtid >> 5;
    int lane = gtid & 31;
    if (node >= N_NODES) return;

    float di = g_dinv[node];
    uint2 sv = reinterpret_cast<const uint2*>(feat + (size_t)node * (DIM / 2))[lane];
    float2 s0 = bf2f(sv.x), s1 = bf2f(sv.y);
    float wsl = di * di;
    float4 acc = make_float4(wsl * s0.x, wsl * s0.y, wsl * s1.x, wsl * s1.y);

    int e0 = g_rowptr[node];
    int e1 = g_rowptr[node + 1];
    for (int eb = e0; eb < e1; eb += 32) {
        int nb = min(32, e1 - eb);
        int2 ew = make_int2(0, 0);
        float wown = 0.0f;
        if (lane < nb) {
            ew = g_edge[eb + lane];
            wown = di * __int_as_float(ew.y);
        }
        for (int j = 0; j < nb; ++j) {
            int sj   = __shfl_sync(0xffffffffu, ew.x, j);
            float wj = __shfl_sync(0xffffffffu, wown, j);
            uint2 d = reinterpret_cast<const uint2*>(feat + (size_t)sj * (DIM / 2))[lane];
            float2 f0 = bf2f(d.x), f1 = bf2f(d.y);
            acc.x += wj * f0.x; acc.y += wj * f0.y;
            acc.z += wj * f1.x; acc.w += wj * f1.y;
        }
    }
    uint2 st;
    st.x = f2bf(acc.x, acc.y);
    st.y = f2bf(acc.z, acc.w);
    reinterpret_cast<uint2*>(out + (size_t)node * (DIM / 2))[lane] = st;
}

// ---------------- tensor-core GEMM: C = relu(A @ W1 + b1), all bf16 I/O ------
// A[M,128] bf16 (packed u32), Wt[n][k] bf16 (g_W1t), C[M,128] bf16.
// Block: 256 thr = 8 warps, tile M=128. Warp w: rows w*16..w*16+15, all 128 cols.
// K chunked by 32; As/Ws pitch 40 halves (80B) => conflict-free LDS.32 frags.
#define LDP 40
__global__ void gemm_mma_bf(const unsigned* __restrict__ A,
                            const float* __restrict__ bias,
                            unsigned* __restrict__ C, int M) {
    __shared__ __nv_bfloat16 As[128][LDP];
    __shared__ __nv_bfloat16 Ws[128][LDP];
    __shared__ float bs[DIM];

    int tid = threadIdx.x;
    int wid = tid >> 5, lane = tid & 31;
    int g = lane >> 2, t = lane & 3;        // mma groupID / thread-in-group
    int row0 = blockIdx.x * 128;
    int wr = wid * 16;

    if (tid < DIM) bs[tid] = bias[tid];

    float acc[16][4];
    #pragma unroll
    for (int nt = 0; nt < 16; ++nt)
        #pragma unroll
        for (int j = 0; j < 4; ++j) acc[nt][j] = 0.0f;

    const unsigned* Wt = g_W1t;

    for (int kc = 0; kc < DIM; kc += 32) {
        // load A chunk: 128 rows x 32 halves (64B/row = 4 x uint4)
        #pragma unroll
        for (int i = 0; i < 2; ++i) {
            int id = i * 256 + tid;          // 0..511
            int r = id >> 2, p = id & 3;
            int grow = min(row0 + r, M - 1);
            uint4 v = *reinterpret_cast<const uint4*>(
                A + (size_t)grow * (DIM / 2) + kc / 2 + p * 4);
            *reinterpret_cast<uint4*>(&As[r][p * 8]) = v;
        }
        // load Wt chunk: 128 n-rows x 32 halves
        #pragma unroll
        for (int i = 0; i < 2; ++i) {
            int id = i * 256 + tid;
            int n = id >> 2, p = id & 3;
            uint4 v = *reinterpret_cast<const uint4*>(
                Wt + (size_t)n * (DIM / 2) + kc / 2 + p * 4);
            *reinterpret_cast<uint4*>(&Ws[n][p * 8]) = v;
        }
        __syncthreads();

        #pragma unroll
        for (int ks = 0; ks < 32; ks += 16) {
            unsigned a0 = *reinterpret_cast<const unsigned*>(&As[wr + g][ks + 2 * t]);
            unsigned a1 = *reinterpret_cast<const unsigned*>(&As[wr + g + 8][ks + 2 * t]);
            unsigned a2 = *reinterpret_cast<const unsigned*>(&As[wr + g][ks + 2 * t + 8]);
            unsigned a3 = *reinterpret_cast<const unsigned*>(&As[wr + g + 8][ks + 2 * t + 8]);
            #pragma unroll
            for (int nt = 0; nt < 16; ++nt) {
                unsigned b0 = *reinterpret_cast<const unsigned*>(&Ws[nt * 8 + g][ks + 2 * t]);
                unsigned b1 = *reinterpret_cast<const unsigned*>(&Ws[nt * 8 + g][ks + 2 * t + 8]);
                asm volatile(
                    "mma.sync.aligned.m16n8k16.row.col.f32.bf16.bf16.f32 "
                    "{%0,%1,%2,%3}, {%4,%5,%6,%7}, {%8,%9}, {%0,%1,%2,%3};\n"
                    : "+f"(acc[nt][0]), "+f"(acc[nt][1]), "+f"(acc[nt][2]), "+f"(acc[nt][3])
                    : "r"(a0), "r"(a1), "r"(a2), "r"(a3), "r"(b0), "r"(b1));
            }
        }
        __syncthreads();
    }

    // epilogue: bias + relu + pack bf16x2, D layout: c0,c1 = D[g][2t,2t+1]; c2,c3 = D[g+8][...]
    int rA = row0 + wr + g;
    int rB = rA + 8;
    #pragma unroll
    for (int nt = 0; nt < 16; ++nt) {
        int col = nt * 8 + 2 * t;
        float bx = bs[col], by = bs[col + 1];
        if (rA < M) {
            float ox = fmaxf(acc[nt][0] + bx, 0.0f);
            float oy = fmaxf(acc[nt][1] + by, 0.0f);
            C[(size_t)rA * (DIM / 2) + col / 2] = f2bf(ox, oy);
        }
        if (rB < M) {
            float ox = fmaxf(acc[nt][2] + bx, 0.0f);
            float oy = fmaxf(acc[nt][3] + by, 0.0f);
            C[(size_t)rB * (DIM / 2) + col / 2] = f2bf(ox, oy);
        }
    }
}

// ---------------- fused mean-pool (sorted batch, bf16 in) + W2 GEMM + b2 -----
__global__ void pool_gemm_kernel(const __nv_bfloat16* __restrict__ feat,
                                 const int* __restrict__ batch,
                                 const float* __restrict__ W2,
                                 const float* __restrict__ b2,
                                 float* __restrict__ out) {
    __shared__ float p[DIM];
    int g = blockIdx.x;
    int j = threadIdx.x;   // 128

    int lo = 0, hi = N_NODES;
    while (lo < hi) { int m = (lo + hi) >> 1; if (batch[m] < g) lo = m + 1; else hi = m; }
    int start = lo;
    hi = N_NODES;
    while (lo < hi) { int m = (lo + hi) >> 1; if (batch[m] < g + 1) lo = m + 1; else hi = m; }
    int end = lo;

    float acc = 0.0f;
    for (int n = start; n < end; ++n)
        acc += __bfloat162float(feat[(size_t)n * DIM + j]);
    float cnt = fmaxf((float)(end - start), 1.0f);
    p[j] = acc / cnt;
    __syncthreads();

    float o = b2[j];
    #pragma unroll 8
    for (int k = 0; k < DIM; ++k)
        o += p[k] * W2[k * DIM + j];
    out[g * DIM + j] = o;
}

// ---------------- launch ----------------
extern "C" void kernel_launch(void* const* d_in, const int* in_sizes, int n_in,
                              void* d_out, int out_size) {
    const float* x     = (const float*)d_in[0];
    const int*   ei    = (const int*)d_in[1];
    const int*   batch = (const int*)d_in[2];
    const float* W1    = (const float*)d_in[3];
    const float* b1    = (const float*)d_in[4];
    const float* W2    = (const float*)d_in[5];
    const float* b2    = (const float*)d_in[6];
    float* out = (float*)d_out;

    const int* src = ei;            // edge_index[0]
    const int* dst = ei + N_EDGES;  // edge_index[1]

    unsigned* bfA; cudaGetSymbolAddress((void**)&bfA, g_bfA);
    unsigned* bfB; cudaGetSymbolAddress((void**)&bfB, g_bfB);

    zero_kernel<<<(N_NODES + 1023) / 1024, 1024>>>();
    tobf16_kernel<<<1024, 256>>>(x, bfA);
    wconv_kernel<<<(DIM * DIM / 2 + 255) / 256, 256>>>(W1);
    hist_kernel<<<2048, 256>>>(dst);
    scanA_kernel<<<SCAN_BLOCKS, 1024>>>();
    scanB_kernel<<<1, 128>>>();
    scanC_kernel<<<SCAN_BLOCKS, 1024>>>();
    fill_kernel<<<2048, 256>>>(src, dst);

    int agg_blocks = (N_NODES * 32 + 255) / 256;
    // layer 1: agg(x_bf16) -> bfB; h1 = relu(bfB @ W1 + b1) -> bfA  (tensor cores)
    agg_kernel_bf<<<agg_blocks, 256>>>(bfA, bfB);
    gemm_mma_bf<<<(N_NODES + 127) / 128, 256>>>(bfB, b1, bfA, N_NODES);

    // layer 2: agg(h1) -> bfB (bf16); W2 deferred past pooling
    agg_kernel_bf<<<agg_blocks, 256>>>(bfA, bfB);

    // fused mean-pool + W2 GEMM + b2
    pool_gemm_kernel<<<N_GRAPHS, DIM>>>(
        reinterpret_cast<const __nv_bfloat16*>(bfB), batch, W2, b2, out);
}

// round 9
// speedup vs baseline: 1.8330x; 1.0195x over previous
#include <cuda_runtime.h>
#include <cuda_fp16.h>
#include <cuda_bf16.h>

// Problem constants
#define N_NODES   100000
#define N_EDGES   1600000
#define DIM       128
#define N_GRAPHS  1024
#define SCAN_BLOCKS 98          // ceil(100000/1024)

// ---------------- scratch (__device__ globals: allocation-free) ----------------
__device__ unsigned g_bfA[(size_t)N_NODES * DIM / 2]; // 25.6 MB bf16x2: x16 / h1
__device__ unsigned g_bfB[(size_t)N_NODES * DIM / 2]; // 25.6 MB bf16x2: agg out
__device__ unsigned g_W1t[DIM * DIM / 2];             // W1^T in bf16: Wt[n][k]
__device__ int2     g_edge[N_EDGES];                  // (src, dinv[src] bits)
__device__ int      g_cnt[N_NODES];
__device__ float    g_dinv[N_NODES];
__device__ int      g_rowptr[N_NODES + 1];
__device__ int      g_cursor[N_NODES];
__device__ unsigned long long g_scan_pack[SCAN_BLOCKS]; // (flag<<32)|value

// bf16x2 (packed u32) -> two fp32: pure ALU (SHF/LOP3)
__device__ __forceinline__ float2 bf2f(unsigned u) {
    float2 r;
    r.x = __uint_as_float(u << 16);
    r.y = __uint_as_float(u & 0xFFFF0000u);
    return r;
}
// two fp32 -> packed bf16x2 (F2FP, fixed-lat pipe)
__device__ __forceinline__ unsigned f2bf(float a, float b) {
    __nv_bfloat162 h = __floats2bfloat162_rn(a, b);
    return *reinterpret_cast<unsigned*>(&h);
}

__device__ __forceinline__ int wsum32(int v) {
    #pragma unroll
    for (int o = 16; o > 0; o >>= 1) v += __shfl_xor_sync(0xffffffffu, v, o);
    return v;
}

// ---------------- fused prep: tobf16(x) | W1 transpose->bf16 | zero cnt/flags --
#define PREP_CONV_BLOCKS 1280
#define PREP_W_BLOCKS    32
#define PREP_Z_BLOCKS    98
__global__ void prep_kernel(const float* __restrict__ x, const float* __restrict__ W1) {
    int b = blockIdx.x;
    int tid = threadIdx.x;
    if (b < PREP_CONV_BLOCKS) {
        // x fp32 -> bf16 packed
        const int total = N_NODES * DIM / 4;
        int stride = PREP_CONV_BLOCKS * 256;
        for (int j = b * 256 + tid; j < total; j += stride) {
            float4 v = reinterpret_cast<const float4*>(x)[j];
            uint2 st;
            st.x = f2bf(v.x, v.y);
            st.y = f2bf(v.z, v.w);
            reinterpret_cast<uint2*>(g_bfA)[j] = st;
        }
    } else if (b < PREP_CONV_BLOCKS + PREP_W_BLOCKS) {
        int i = (b - PREP_CONV_BLOCKS) * 256 + tid;   // 0..8191
        int n = i >> 6;
        int k2 = (i & 63) * 2;
        float a = W1[(size_t)k2 * DIM + n];
        float c = W1[(size_t)(k2 + 1) * DIM + n];
        g_W1t[i] = f2bf(a, c);
    } else {
        int base = (b - PREP_CONV_BLOCKS - PREP_W_BLOCKS) * 256 + tid;
        int stride = PREP_Z_BLOCKS * 256;
        for (int j = base; j < N_NODES; j += stride) g_cnt[j] = 0;
        if (base < SCAN_BLOCKS) g_scan_pack[base] = 0ULL;
    }
}

// ---------------- degree histogram over dst ----------------
__global__ void hist_kernel(const int* __restrict__ dst) {
    int i = blockIdx.x * blockDim.x + threadIdx.x;
    int stride = gridDim.x * blockDim.x;
    for (int e = i; e < N_EDGES; e += stride)
        atomicAdd(&g_cnt[dst[e]], 1);
}

// ---------------- single-pass scan: decoupled lookback + dinv + cursor -------
__global__ void scan_kernel() {
    __shared__ int warp_sums[32];
    __shared__ int s_prefix;
    int tid = threadIdx.x, lane = tid & 31, wid = tid >> 5;
    int b = blockIdx.x;
    int i = b * 1024 + tid;
    int v = (i < N_NODES) ? g_cnt[i] : 0;
    if (i < N_NODES) g_dinv[i] = rsqrtf((float)(v + 1));

    // local exclusive scan
    int x = v;
    #pragma unroll
    for (int o = 1; o < 32; o <<= 1) {
        int t = __shfl_up_sync(0xffffffffu, x, o);
        if (lane >= o) x += t;
    }
    if (lane == 31) warp_sums[wid] = x;
    __syncthreads();
    if (wid == 0) {
        int s = warp_sums[lane];
        #pragma unroll
        for (int o = 1; o < 32; o <<= 1) {
            int t = __shfl_up_sync(0xffffffffu, s, o);
            if (lane >= o) s += t;
        }
        warp_sums[lane] = s;
    }
    __syncthreads();
    int excl = (wid > 0 ? warp_sums[wid - 1] : 0) + x - v;
    int total = warp_sums[31];

    // publish aggregate (or inclusive for block 0)
    if (tid == 0) {
        unsigned long long p = (b == 0)
            ? ((2ULL << 32) | (unsigned)total)
            : ((1ULL << 32) | (unsigned)total);
        atomicExch(&g_scan_pack[b], p);
    }

    // warp 0: decoupled lookback (32 predecessors per round)
    if (wid == 0) {
        int prefix = 0;
        if (b > 0) {
            int offset = 0;
            bool done = false;
            while (!done) {
                int my = b - 1 - offset - lane;
                int f = 2, val = 0;
                if (my >= 0) {
                    unsigned long long pv;
                    do {
                        pv = *((volatile unsigned long long*)&g_scan_pack[my]);
                        f = (int)(pv >> 32);
                    } while (f == 0);
                    val = (int)(pv & 0xffffffffULL);
                }
                unsigned m = __ballot_sync(0xffffffffu, f == 2);
                if (m == 0) {
                    prefix += wsum32(val);
                    offset += 32;
                } else {
                    int first = __ffs(m) - 1;
                    int c = (lane <= first) ? val : 0;
                    prefix += wsum32(c);
                    done = true;
                }
            }
        }
        if (lane == 0) {
            s_prefix = prefix;
            atomicExch(&g_scan_pack[b], (2ULL << 32) | (unsigned)(prefix + total));
        }
    }
    __syncthreads();
    int prefix = s_prefix;
    if (i < N_NODES) {
        int r = excl + prefix;
        g_rowptr[i] = r;
        g_cursor[i] = r;
    }
    if (b == 0 && tid == 0) g_rowptr[N_NODES] = N_EDGES;
}

// ---------------- counting-sort fill: (src, dinv[src]) records -------------
__global__ void fill_kernel(const int* __restrict__ src, const int* __restrict__ dst) {
    int i = blockIdx.x * blockDim.x + threadIdx.x;
    int stride = gridDim.x * blockDim.x;
    for (int e = i; e < N_EDGES; e += stride) {
        int d = dst[e];
        int s = src[e];
        int pos = atomicAdd(&g_cursor[d], 1);
        g_edge[pos] = make_int2(s, __float_as_int(g_dinv[s]));
    }
}

// ---------------- aggregation (bf16 gather, fp32 accumulate, bf16 out) ------
__global__ void agg_kernel_bf(const unsigned* __restrict__ feat, unsigned* __restrict__ out) {
    int gtid = blockIdx.x * blockDim.x + threadIdx.x;
    int node = gtid >> 5;
    int lane = gtid & 31;
    if (node >= N_NODES) return;

    float di = g_dinv[node];
    uint2 sv = reinterpret_cast<const uint2*>(feat + (size_t)node * (DIM / 2))[lane];
    float2 s0 = bf2f(sv.x), s1 = bf2f(sv.y);
    float wsl = di * di;
    float4 acc = make_float4(wsl * s0.x, wsl * s0.y, wsl * s1.x, wsl * s1.y);

    int e0 = g_rowptr[node];
    int e1 = g_rowptr[node + 1];
    for (int eb = e0; eb < e1; eb += 32) {
        int nb = min(32, e1 - eb);
        int2 ew = make_int2(0, 0);
        float wown = 0.0f;
        if (lane < nb) {
            ew = g_edge[eb + lane];
            wown = di * __int_as_float(ew.y);
        }
        for (int j = 0; j < nb; ++j) {
            int sj   = __shfl_sync(0xffffffffu, ew.x, j);
            float wj = __shfl_sync(0xffffffffu, wown, j);
            uint2 d = reinterpret_cast<const uint2*>(feat + (size_t)sj * (DIM / 2))[lane];
            float2 f0 = bf2f(d.x), f1 = bf2f(d.y);
            acc.x += wj * f0.x; acc.y += wj * f0.y;
            acc.z += wj * f1.x; acc.w += wj * f1.y;
        }
    }
    uint2 st;
    st.x = f2bf(acc.x, acc.y);
    st.y = f2bf(acc.z, acc.w);
    reinterpret_cast<uint2*>(out + (size_t)node * (DIM / 2))[lane] = st;
}

// ---------------- tensor-core GEMM: C = relu(A @ W1 + b1), bf16 I/O ----------
// K chunked by 64; pitch 72 halves (144B) => conflict-free 4B fragment LDS.
#define LDP 72
__global__ void gemm_mma_bf(const unsigned* __restrict__ A,
                            const float* __restrict__ bias,
                            unsigned* __restrict__ C, int M) {
    __shared__ __nv_bfloat16 As[128][LDP];
    __shared__ __nv_bfloat16 Ws[128][LDP];
    __shared__ float bs[DIM];

    int tid = threadIdx.x;
    int wid = tid >> 5, lane = tid & 31;
    int g = lane >> 2, t = lane & 3;
    int row0 = blockIdx.x * 128;
    int wr = wid * 16;

    if (tid < DIM) bs[tid] = bias[tid];

    float acc[16][4];
    #pragma unroll
    for (int nt = 0; nt < 16; ++nt)
        #pragma unroll
        for (int j = 0; j < 4; ++j) acc[nt][j] = 0.0f;

    const unsigned* Wt = g_W1t;

    #pragma unroll
    for (int kc = 0; kc < DIM; kc += 64) {
        // A chunk: 128 rows x 64 halves (128B/row = 8 uint4); 1024 uint4, 4/thread
        #pragma unroll
        for (int i = 0; i < 4; ++i) {
            int id = i * 256 + tid;
            int r = id >> 3, p = id & 7;
            int grow = min(row0 + r, M - 1);
            uint4 v = *reinterpret_cast<const uint4*>(
                A + (size_t)grow * (DIM / 2) + kc / 2 + p * 4);
            *reinterpret_cast<uint4*>(&As[r][p * 8]) = v;
        }
        // W chunk
        #pragma unroll
        for (int i = 0; i < 4; ++i) {
            int id = i * 256 + tid;
            int n = id >> 3, p = id & 7;
            uint4 v = *reinterpret_cast<const uint4*>(
                Wt + (size_t)n * (DIM / 2) + kc / 2 + p * 4);
            *reinterpret_cast<uint4*>(&Ws[n][p * 8]) = v;
        }
        __syncthreads();

        #pragma unroll
        for (int ks = 0; ks < 64; ks += 16) {
            unsigned a0 = *reinterpret_cast<const unsigned*>(&As[wr + g][ks + 2 * t]);
            unsigned a1 = *reinterpret_cast<const unsigned*>(&As[wr + g + 8][ks + 2 * t]);
            unsigned a2 = *reinterpret_cast<const unsigned*>(&As[wr + g][ks + 2 * t + 8]);
            unsigned a3 = *reinterpret_cast<const unsigned*>(&As[wr + g + 8][ks + 2 * t + 8]);
            #pragma unroll
            for (int nt = 0; nt < 16; ++nt) {
                unsigned b0 = *reinterpret_cast<const unsigned*>(&Ws[nt * 8 + g][ks + 2 * t]);
                unsigned b1 = *reinterpret_cast<const unsigned*>(&Ws[nt * 8 + g][ks + 2 * t + 8]);
                asm volatile(
                    "mma.sync.aligned.m16n8k16.row.col.f32.bf16.bf16.f32 "
                    "{%0,%1,%2,%3}, {%4,%5,%6,%7}, {%8,%9}, {%0,%1,%2,%3};\n"
                    : "+f"(acc[nt][0]), "+f"(acc[nt][1]), "+f"(acc[nt][2]), "+f"(acc[nt][3])
                    : "r"(a0), "r"(a1), "r"(a2), "r"(a3), "r"(b0), "r"(b1));
            }
        }
        __syncthreads();
    }

    int rA = row0 + wr + g;
    int rB = rA + 8;
    #pragma unroll
    for (int nt = 0; nt < 16; ++nt) {
        int col = nt * 8 + 2 * t;
        float bx = bs[col], by = bs[col + 1];
        if (rA < M) {
            float ox = fmaxf(acc[nt][0] + bx, 0.0f);
            float oy = fmaxf(acc[nt][1] + by, 0.0f);
            C[(size_t)rA * (DIM / 2) + col / 2] = f2bf(ox, oy);
        }
        if (rB < M) {
            float ox = fmaxf(acc[nt][2] + bx, 0.0f);
            float oy = fmaxf(acc[nt][3] + by, 0.0f);
            C[(size_t)rB * (DIM / 2) + col / 2] = f2bf(ox, oy);
        }
    }
}

// ---------------- fused mean-pool (sorted batch, bf16 in) + W2 GEMM + b2 -----
// 128 thr: q=tid>>5 row-group, l=tid&31 owns 4 features; 4 rows in flight.
__global__ void pool_gemm_kernel(const uint2* __restrict__ feat2,
                                 const int* __restrict__ batch,
                                 const float* __restrict__ W2,
                                 const float* __restrict__ b2,
                                 float* __restrict__ out) {
    __shared__ float4 sa[4][32];
    __shared__ float p[DIM];
    int g = blockIdx.x;
    int tid = threadIdx.x;
    int q = tid >> 5, l = tid & 31;

    int lo = 0, hi = N_NODES;
    while (lo < hi) { int m = (lo + hi) >> 1; if (batch[m] < g) lo = m + 1; else hi = m; }
    int start = lo;
    hi = N_NODES;
    while (lo < hi) { int m = (lo + hi) >> 1; if (batch[m] < g + 1) lo = m + 1; else hi = m; }
    int end = lo;

    float4 acc = make_float4(0.f, 0.f, 0.f, 0.f);
    for (int n = start + q; n < end; n += 4) {
        uint2 d = feat2[(size_t)n * (DIM / 4) + l];   // 32 uint2 per row
        float2 f0 = bf2f(d.x), f1 = bf2f(d.y);
        acc.x += f0.x; acc.y += f0.y; acc.z += f1.x; acc.w += f1.y;
    }
    sa[q][l] = acc;
    __syncthreads();
    if (q == 0) {
        float4 s = sa[0][l];
        #pragma unroll
        for (int r = 1; r < 4; ++r) {
            float4 v = sa[r][l];
            s.x += v.x; s.y += v.y; s.z += v.z; s.w += v.w;
        }
        float cnt = fmaxf((float)(end - start), 1.0f);
        p[l * 4 + 0] = s.x / cnt;
        p[l * 4 + 1] = s.y / cnt;
        p[l * 4 + 2] = s.z / cnt;
        p[l * 4 + 3] = s.w / cnt;
    }
    __syncthreads();

    int j = tid;
    float o = b2[j];
    #pragma unroll 8
    for (int k = 0; k < DIM; ++k)
        o += p[k] * W2[k * DIM + j];
    out[g * DIM + j] = o;
}

// ---------------- launch ----------------
extern "C" void kernel_launch(void* const* d_in, const int* in_sizes, int n_in,
                              void* d_out, int out_size) {
    const float* x     = (const float*)d_in[0];
    const int*   ei    = (const int*)d_in[1];
    const int*   batch = (const int*)d_in[2];
    const float* W1    = (const float*)d_in[3];
    const float* b1    = (const float*)d_in[4];
    const float* W2    = (const float*)d_in[5];
    const float* b2    = (const float*)d_in[6];
    float* out = (float*)d_out;

    const int* src = ei;            // edge_index[0]
    const int* dst = ei + N_EDGES;  // edge_index[1]

    unsigned* bfA; cudaGetSymbolAddress((void**)&bfA, g_bfA);
    unsigned* bfB; cudaGetSymbolAddress((void**)&bfB, g_bfB);

    prep_kernel<<<PREP_CONV_BLOCKS + PREP_W_BLOCKS + PREP_Z_BLOCKS, 256>>>(x, W1);
    hist_kernel<<<2048, 256>>>(dst);
    scan_kernel<<<SCAN_BLOCKS, 1024>>>();
    fill_kernel<<<2048, 256>>>(src, dst);

    int agg_blocks = (N_NODES * 32 + 255) / 256;
    // layer 1: agg(x_bf16) -> bfB; h1 = relu(bfB @ W1 + b1) -> bfA  (tensor cores)
    agg_kernel_bf<<<agg_blocks, 256>>>(bfA, bfB);
    gemm_mma_bf<<<(N_NODES + 127) / 128, 256>>>(bfB, b1, bfA, N_NODES);

    // layer 2: agg(h1) -> bfB (bf16); W2 deferred past pooling
    agg_kernel_bf<<<agg_blocks, 256>>>(bfA, bfB);

    // fused mean-pool + W2 GEMM + b2
    pool_gemm_kernel<<<N_GRAPHS, DIM>>>(
        reinterpret_cast<const uint2*>(bfB), batch, W2, b2, out);
}